// round 5
// baseline (speedup 1.0000x reference)
#include <cuda_runtime.h>
#include <cstdint>

// Gated delta rule recurrence: S_t = S_{t-1} @ A_t + B_t
// 128 CTAs (2 per chain, 32 rows each) x 256 threads (2 warps/SMSP for latency hiding).
// Warp tile: 16 rows x 16 cols; thread tile: 2 rows x 4 cols.
// Per k per thread: 1 LDS.128 Sdup (both rows, duplicated pairs) +
//                   1 LDS.128 A (4 cols as 2 f32x2 operands) + 4 fma.rn.f32x2.
// Wavefronts: 2/warp/k (S:128B bcast, A:64B) -> 1024 wf/step == fma floor.

#define T_DIM 128
#define BH 64
#define D 64
#define ROWS 32
#define THREADS 256
#define TSTRIDE (BH * D * D)

#define A_FLOATS (D * D)            // 16 KB per buffer
#define S_ULLS   (D * ROWS)         // 16 KB per buffer (dup pairs)
#define SMEM_BYTES (2 * A_FLOATS * 4 + 2 * S_ULLS * 8)   // 65536

__device__ __forceinline__ uint32_t smem_u32(const void* p) {
    return (uint32_t)__cvta_generic_to_shared(p);
}
__device__ __forceinline__ unsigned long long pk2(float lo, float hi) {
    unsigned long long r;
    asm("mov.b64 %0,{%1,%2};" : "=l"(r) : "f"(lo), "f"(hi));
    return r;
}
__device__ __forceinline__ void upk2(unsigned long long v, float& lo, float& hi) {
    asm("mov.b64 {%0,%1},%2;" : "=f"(lo), "=f"(hi) : "l"(v));
}
__device__ __forceinline__ unsigned long long f2fma(unsigned long long a,
                                                    unsigned long long b,
                                                    unsigned long long c) {
    unsigned long long d;
    asm("fma.rn.f32x2 %0,%1,%2,%3;" : "=l"(d) : "l"(a), "l"(b), "l"(c));
    return d;
}

__global__ void __launch_bounds__(THREADS, 1) gdr_kernel(
    const float* __restrict__ A,
    const float* __restrict__ Bm,
    const float* __restrict__ S0,
    float* __restrict__ out)
{
    extern __shared__ char smem[];
    float* Abuf0 = (float*)smem;
    float* Abuf1 = (float*)(smem + A_FLOATS * 4);
    unsigned long long* Sdup0 = (unsigned long long*)(smem + 2 * A_FLOATS * 4);
    unsigned long long* Sdup1 = Sdup0 + S_ULLS;

    const int tid   = threadIdx.x;
    const int chain = blockIdx.x >> 1;
    const int half  = blockIdx.x & 1;
    const int r0base = half * ROWS;

    // warp tile: 16 rows x 16 cols. wid bit0 -> row half, bits[1:2] -> col quarter.
    const int wid  = tid >> 5;
    const int lane = tid & 31;
    const int wr   = wid & 1;            // 0,1: rows [0..15] or [16..31]
    const int wc   = wid >> 1;           // 0..3: cols 16*wc
    const int rgl  = lane & 7;           // row pair within warp
    const int cgl  = lane >> 3;          // 0..3: 4-col group within warp

    const int rl0 = wr * 16 + rgl * 2;   // local row (even), 0..30
    const int c   = wc * 16 + cgl * 4;   // col base, 0..60

    const long chainOff = (long)chain * (D * D);

    // ---- prologue: A[0] via cp.async (16 KB, 256 threads x 4 x 16B) ----
    {
        uint32_t s = smem_u32(Abuf0) + tid * 16;
        const float* g = A + chainOff + tid * 4;
        #pragma unroll
        for (int i = 0; i < 4; i++) {
            asm volatile("cp.async.cg.shared.global [%0],[%1],16;"
                         :: "r"(s + i * 4096), "l"(g + i * 1024));
        }
        asm volatile("cp.async.commit_group;");
    }

    // Bm[0] -> registers (2 rows x 4 cols)
    float4 bm0, bm1;
    {
        const float* g = Bm + chainOff + (long)(r0base + rl0) * D + c;
        bm0 = *(const float4*)(g);
        bm1 = *(const float4*)(g + D);
    }

    // Init Sdup0[k*ROWS + r] = (S0[r][k], S0[r][k])
    {
        int rl = tid & 31;
        int kb = (tid >> 5) * 8;
        const float* g = S0 + chainOff + (long)(r0base + rl) * D + kb;
        #pragma unroll
        for (int kk = 0; kk < 8; kk++) {
            float v = g[kk];
            Sdup0[(kb + kk) * ROWS + rl] = pk2(v, v);
        }
    }

    // ---- main time loop ----
    for (int t = 0; t < T_DIM; t++) {
        asm volatile("cp.async.wait_group 0;" ::: "memory");
        __syncthreads();   // publishes A[t] and Sdup[cur]

        const int cur = t & 1;
        float* Acur  = cur ? Abuf1 : Abuf0;
        float* Anext = cur ? Abuf0 : Abuf1;
        unsigned long long* Scur  = cur ? Sdup1 : Sdup0;
        unsigned long long* Snext = cur ? Sdup0 : Sdup1;

        // prefetch A[t+1]
        if (t + 1 < T_DIM) {
            uint32_t s = smem_u32(Anext) + tid * 16;
            const float* g = A + (long)(t + 1) * TSTRIDE + chainOff + tid * 4;
            #pragma unroll
            for (int i = 0; i < 4; i++) {
                asm volatile("cp.async.cg.shared.global [%0],[%1],16;"
                             :: "r"(s + i * 4096), "l"(g + i * 1024));
            }
            asm volatile("cp.async.commit_group;");
        }

        // acc := Bm[t]
        unsigned long long a00, a01, a10, a11;
        a00 = pk2(bm0.x, bm0.y); a01 = pk2(bm0.z, bm0.w);
        a10 = pk2(bm1.x, bm1.y); a11 = pk2(bm1.z, bm1.w);

        // prefetch Bm[t+1] (overlaps k-loop)
        if (t + 1 < T_DIM) {
            const float* g = Bm + (long)(t + 1) * TSTRIDE + chainOff
                           + (long)(r0base + rl0) * D + c;
            bm0 = *(const float4*)(g);
            bm1 = *(const float4*)(g + D);
        }

        // k-loop: 6 instrs per k (2 LDS.128 + 4 f2fma), immediate offsets
        const ulonglong2* __restrict__ Ap = (const ulonglong2*)(Acur + c);
        const ulonglong2* __restrict__ Sp = (const ulonglong2*)(Scur + rl0);

        #pragma unroll
        for (int k = 0; k < D; k++) {
            ulonglong2 sv = Sp[k * 16];     // (s_r0,s_r0),(s_r1,s_r1)
            ulonglong2 av = Ap[k * 16];     // A[k][c..c+3] as 2 packed pairs
            a00 = f2fma(sv.x, av.x, a00);
            a01 = f2fma(sv.x, av.y, a01);
            a10 = f2fma(sv.y, av.x, a10);
            a11 = f2fma(sv.y, av.y, a11);
        }

        // epilogue
        float r0f[4], r1f[4];
        upk2(a00, r0f[0], r0f[1]); upk2(a01, r0f[2], r0f[3]);
        upk2(a10, r1f[0], r1f[1]); upk2(a11, r1f[2], r1f[3]);

        float* o = out + (long)t * TSTRIDE + chainOff
                 + (long)(r0base + rl0) * D + c;
        *(float4*)(o)     = make_float4(r0f[0], r0f[1], r0f[2], r0f[3]);
        *(float4*)(o + D) = make_float4(r1f[0], r1f[1], r1f[2], r1f[3]);

        // Snew -> Sdup[next]: col j becomes next step's k
        if (t + 1 < T_DIM) {
            #pragma unroll
            for (int jj = 0; jj < 4; jj++) {
                ulonglong2 w;
                w.x = pk2(r0f[jj], r0f[jj]);
                w.y = pk2(r1f[jj], r1f[jj]);
                *(ulonglong2*)&Snext[(c + jj) * ROWS + rl0] = w;
            }
        }
    }
}

extern "C" void kernel_launch(void* const* d_in, const int* in_sizes, int n_in,
                              void* d_out, int out_size) {
    const float* A  = (const float*)d_in[0];
    const float* Bm = (const float*)d_in[1];
    const float* S0 = (const float*)d_in[2];
    float* out = (float*)d_out;
    (void)in_sizes; (void)n_in; (void)out_size;

    cudaFuncSetAttribute(gdr_kernel,
                         cudaFuncAttributeMaxDynamicSharedMemorySize,
                         SMEM_BYTES);
    gdr_kernel<<<BH * 2, THREADS, SMEM_BYTES>>>(A, Bm, S0, out);
}

// round 6
// speedup vs baseline: 1.3781x; 1.3781x over previous
#include <cuda_runtime.h>
#include <cstdint>

// Gated delta rule: S_t = S_{t-1} @ A_t + B_t.  T=128, 64 chains, D=64.
// Crossbar-byte-optimal layout: 128 CTAs (32 rows) x 128 threads,
// thread tile 4 contiguous rows x 4 cols.
// Per k: 1 LDS.128 (4 S values, row-pair packed) + 2 LDS.64 (4 A scalars)
//        + 4 pk2 movs (ALU) + 8 fma.rn.f32x2  ->  8 crossbar cyc/warp/k
//        -> 2048 crossbar cyc/step/SM (2x the fma floor of 1024).
// S smem [k][r], row padded to 36 floats (bank rotation, 16B aligned).
// Out stores deferred one step (read from smem after the sync), coalesced.

#define T_DIM 128
#define BH 64
#define D 64
#define ROWS 32
#define THREADS 128
#define TSTRIDE (BH * D * D)
#define SROW 36
#define A_BYTES (D * D * 4)              // 16384
#define S_BYTES (D * SROW * 4)           // 9216
#define SMEM_BYTES (2 * A_BYTES + 2 * S_BYTES)   // 51200

__device__ __forceinline__ uint32_t smem_u32(const void* p) {
    return (uint32_t)__cvta_generic_to_shared(p);
}
__device__ __forceinline__ unsigned long long pk2(float lo, float hi) {
    unsigned long long r;
    asm("mov.b64 %0,{%1,%2};" : "=l"(r) : "f"(lo), "f"(hi));
    return r;
}
__device__ __forceinline__ unsigned long long f2fma(unsigned long long a,
                                                    unsigned long long b,
                                                    unsigned long long c) {
    unsigned long long d;
    asm("fma.rn.f32x2 %0,%1,%2,%3;" : "=l"(d) : "l"(a), "l"(b), "l"(c));
    return d;
}

__global__ void __launch_bounds__(THREADS, 1) gdr_kernel(
    const float* __restrict__ A,
    const float* __restrict__ Bm,
    const float* __restrict__ S0,
    float* __restrict__ out)
{
    extern __shared__ char smem[];
    float* Ab0 = (float*)smem;                       // 16 KB
    float* Ab1 = (float*)(smem + A_BYTES);           // 16 KB
    float* Sb0 = (float*)(smem + 2 * A_BYTES);       // 9216 B, [k][r] pad 36
    float* Sb1 = (float*)(smem + 2 * A_BYTES + S_BYTES);

    const int tid   = threadIdx.x;
    const int chain = blockIdx.x >> 1;
    const int half  = blockIdx.x & 1;
    const int r0base = half * ROWS;

    const int rg = tid & 7;          // row group: rows 4rg..4rg+3
    const int cg = tid >> 3;         // 0..15
    const int c0 = cg * 4;           // col base
    const int r0 = rg * 4;           // local row base (contiguous 4)

    // out-store mapping (2 rows x 8 cols per thread)
    const int om = tid & 15;         // row pair 2om, 2om+1
    const int ocg = tid >> 4;        // col group *8

    const long chainOff = (long)chain * (D * D);

    // ---- prologue: A[0] via cp.async ----
    {
        uint32_t s = smem_u32(Ab0) + tid * 16;
        const float* g = A + chainOff + tid * 4;
        #pragma unroll
        for (int i = 0; i < 8; i++) {
            asm volatile("cp.async.cg.shared.global [%0],[%1],16;"
                         :: "r"(s + i * 2048), "l"(g + i * 512));
        }
        asm volatile("cp.async.commit_group;");
    }

    // Bm[0] -> registers (4 rows x 4 cols)
    float4 q0, q1, q2, q3;
    {
        const float* g = Bm + chainOff + (long)(r0base + r0) * D + c0;
        q0 = *(const float4*)(g);
        q1 = *(const float4*)(g + D);
        q2 = *(const float4*)(g + 2 * D);
        q3 = *(const float4*)(g + 3 * D);
    }

    // Init Sb0[k*SROW + r] = S0[r][k]
    {
        int rl = tid & 31;
        int kb = (tid >> 5) * 16;
        const float* g = S0 + chainOff + (long)(r0base + rl) * D + kb;
        #pragma unroll
        for (int kk = 0; kk < 16; kk++)
            Sb0[(kb + kk) * SROW + rl] = g[kk];
    }

    // ---- main time loop ----
    for (int t = 0; t < T_DIM; t++) {
        asm volatile("cp.async.wait_group 0;" ::: "memory");
        __syncthreads();   // publishes A[t] and S_{t-1} smem

        const int cur = t & 1;
        float* Acur  = cur ? Ab1 : Ab0;
        float* Anext = cur ? Ab0 : Ab1;
        float* Scur  = cur ? Sb1 : Sb0;
        float* Snext = cur ? Sb0 : Sb1;

        // prefetch A[t+1]
        if (t + 1 < T_DIM) {
            uint32_t s = smem_u32(Anext) + tid * 16;
            const float* g = A + (long)(t + 1) * TSTRIDE + chainOff + tid * 4;
            #pragma unroll
            for (int i = 0; i < 8; i++) {
                asm volatile("cp.async.cg.shared.global [%0],[%1],16;"
                             :: "r"(s + i * 2048), "l"(g + i * 512));
            }
            asm volatile("cp.async.commit_group;");
        }

        // deferred out-store of step t-1 (reads Scur = S_{t-1}, conflict-free)
        if (t > 0) {
            uint32_t rb = smem_u32(Scur) + om * 8;   // r = 2*om -> byte off 8*om
            float v0,v1,v2,v3,v4,v5,v6,v7,v8,v9,v10,v11,v12,v13,v14,v15;
            #define OLD(i, lo, hi) \
                asm("ld.shared.v2.f32 {%0,%1},[%2];" : "=f"(lo), "=f"(hi) \
                    : "r"(rb + (ocg * 8 + i) * (SROW * 4)))
            OLD(0, v0, v1);  OLD(1, v2, v3);  OLD(2, v4, v5);  OLD(3, v6, v7);
            OLD(4, v8, v9);  OLD(5, v10, v11); OLD(6, v12, v13); OLD(7, v14, v15);
            #undef OLD
            float* o = out + (long)(t - 1) * TSTRIDE + chainOff
                     + (long)(r0base + 2 * om) * D + ocg * 8;
            *(float4*)(o)     = make_float4(v0, v2, v4, v6);
            *(float4*)(o + 4) = make_float4(v8, v10, v12, v14);
            *(float4*)(o + D)     = make_float4(v1, v3, v5, v7);
            *(float4*)(o + D + 4) = make_float4(v9, v11, v13, v15);
        }

        // acc := Bm[t] (row-pair packed per column)
        unsigned long long aA0, aA1, aA2, aA3, aB0, aB1, aB2, aB3;
        aA0 = pk2(q0.x, q1.x); aA1 = pk2(q0.y, q1.y);
        aA2 = pk2(q0.z, q1.z); aA3 = pk2(q0.w, q1.w);
        aB0 = pk2(q2.x, q3.x); aB1 = pk2(q2.y, q3.y);
        aB2 = pk2(q2.z, q3.z); aB3 = pk2(q2.w, q3.w);

        // prefetch Bm[t+1]
        if (t + 1 < T_DIM) {
            const float* g = Bm + (long)(t + 1) * TSTRIDE + chainOff
                           + (long)(r0base + r0) * D + c0;
            q0 = *(const float4*)(g);
            q1 = *(const float4*)(g + D);
            q2 = *(const float4*)(g + 2 * D);
            q3 = *(const float4*)(g + 3 * D);
        }

        // k-loop: 1 LDS.128 (S, 4 rows) + 2 LDS.64 (A, 4 cols) + 4 mov + 8 f2fma
        const uint32_t sA = smem_u32(Scur) + r0 * 4;
        const uint32_t aA = smem_u32(Acur) + c0 * 4;
        #pragma unroll
        for (int k = 0; k < D; k++) {
            unsigned long long svx, svy;
            asm("ld.shared.v2.u64 {%0,%1},[%2];"
                : "=l"(svx), "=l"(svy) : "r"(sA + k * (SROW * 4)));
            float a0, a1, a2, a3;
            asm("ld.shared.v2.f32 {%0,%1},[%2];"
                : "=f"(a0), "=f"(a1) : "r"(aA + k * 256));
            asm("ld.shared.v2.f32 {%0,%1},[%2];"
                : "=f"(a2), "=f"(a3) : "r"(aA + k * 256 + 8));
            unsigned long long d0 = pk2(a0, a0);
            unsigned long long d1 = pk2(a1, a1);
            unsigned long long d2 = pk2(a2, a2);
            unsigned long long d3 = pk2(a3, a3);
            aA0 = f2fma(svx, d0, aA0);
            aA1 = f2fma(svx, d1, aA1);
            aA2 = f2fma(svx, d2, aA2);
            aA3 = f2fma(svx, d3, aA3);
            aB0 = f2fma(svy, d0, aB0);
            aB1 = f2fma(svy, d1, aB1);
            aB2 = f2fma(svy, d2, aB2);
            aB3 = f2fma(svy, d3, aB3);
        }

        // Snew -> Snext[c][r]: acc pairs are already the [c][r0..r0+4] layout
        {
            uint32_t stB = smem_u32(Snext) + c0 * (SROW * 4) + r0 * 4;
            asm volatile("st.shared.v2.u64 [%0],{%1,%2};"
                         :: "r"(stB), "l"(aA0), "l"(aB0));
            asm volatile("st.shared.v2.u64 [%0],{%1,%2};"
                         :: "r"(stB + SROW * 4), "l"(aA1), "l"(aB1));
            asm volatile("st.shared.v2.u64 [%0],{%1,%2};"
                         :: "r"(stB + 2 * SROW * 4), "l"(aA2), "l"(aB2));
            asm volatile("st.shared.v2.u64 [%0],{%1,%2};"
                         :: "r"(stB + 3 * SROW * 4), "l"(aA3), "l"(aB3));
        }
    }

    // final out-store for t = T-1 (state sits in Sb[T_DIM & 1])
    __syncthreads();
    {
        float* Slast = (T_DIM & 1) ? Sb1 : Sb0;
        uint32_t rb = smem_u32(Slast) + om * 8;
        float v0,v1,v2,v3,v4,v5,v6,v7,v8,v9,v10,v11,v12,v13,v14,v15;
        #define OLD(i, lo, hi) \
            asm("ld.shared.v2.f32 {%0,%1},[%2];" : "=f"(lo), "=f"(hi) \
                : "r"(rb + (ocg * 8 + i) * (SROW * 4)))
        OLD(0, v0, v1);  OLD(1, v2, v3);  OLD(2, v4, v5);  OLD(3, v6, v7);
        OLD(4, v8, v9);  OLD(5, v10, v11); OLD(6, v12, v13); OLD(7, v14, v15);
        #undef OLD
        float* o = out + (long)(T_DIM - 1) * TSTRIDE + chainOff
                 + (long)(r0base + 2 * om) * D + ocg * 8;
        *(float4*)(o)     = make_float4(v0, v2, v4, v6);
        *(float4*)(o + 4) = make_float4(v8, v10, v12, v14);
        *(float4*)(o + D)     = make_float4(v1, v3, v5, v7);
        *(float4*)(o + D + 4) = make_float4(v9, v11, v13, v15);
    }
}

extern "C" void kernel_launch(void* const* d_in, const int* in_sizes, int n_in,
                              void* d_out, int out_size) {
    const float* A  = (const float*)d_in[0];
    const float* Bm = (const float*)d_in[1];
    const float* S0 = (const float*)d_in[2];
    float* out = (float*)d_out;
    (void)in_sizes; (void)n_in; (void)out_size;

    cudaFuncSetAttribute(gdr_kernel,
                         cudaFuncAttributeMaxDynamicSharedMemorySize,
                         SMEM_BYTES);
    gdr_kernel<<<BH * 2, THREADS, SMEM_BYTES>>>(A, Bm, S0, out);
}

// round 8
// speedup vs baseline: 1.3910x; 1.0094x over previous
#include <cuda_runtime.h>
#include <cstdint>

// Gated delta rule: S_t = S_{t-1} @ A_t + B_t.  T=128, 64 chains, D=64.
// 128 CTAs (2 per chain, 32 rows) x 128 threads, thread tile 4 rows x 4 cols.
// R7: manual 2-stage software pipeline over k (16 chunks of 4) so LDS latency
// is hidden even with 1 warp/SMSP. Math order identical to R6 (k ascending).

#define T_DIM 128
#define BH 64
#define D 64
#define ROWS 32
#define THREADS 128
#define TSTRIDE (BH * D * D)
#define SROW 36
#define A_BYTES (D * D * 4)              // 16384
#define S_BYTES (D * SROW * 4)           // 9216
#define SMEM_BYTES (2 * A_BYTES + 2 * S_BYTES)   // 51200

__device__ __forceinline__ uint32_t smem_u32(const void* p) {
    return (uint32_t)__cvta_generic_to_shared(p);
}
__device__ __forceinline__ unsigned long long pk2(float lo, float hi) {
    unsigned long long r;
    asm("mov.b64 %0,{%1,%2};" : "=l"(r) : "f"(lo), "f"(hi));
    return r;
}
__device__ __forceinline__ unsigned long long f2fma(unsigned long long a,
                                                    unsigned long long b,
                                                    unsigned long long c) {
    unsigned long long d;
    asm("fma.rn.f32x2 %0,%1,%2,%3;" : "=l"(d) : "l"(a), "l"(b), "l"(c));
    return d;
}

__global__ void __launch_bounds__(THREADS, 1) gdr_kernel(
    const float* __restrict__ A,
    const float* __restrict__ Bm,
    const float* __restrict__ S0,
    float* __restrict__ out)
{
    extern __shared__ char smem[];
    float* Ab0 = (float*)smem;
    float* Ab1 = (float*)(smem + A_BYTES);
    float* Sb0 = (float*)(smem + 2 * A_BYTES);
    float* Sb1 = (float*)(smem + 2 * A_BYTES + S_BYTES);

    const int tid   = threadIdx.x;
    const int chain = blockIdx.x >> 1;
    const int half  = blockIdx.x & 1;
    const int r0base = half * ROWS;

    const int rg = tid & 7;          // rows 4rg..4rg+3
    const int cg = tid >> 3;         // 0..15
    const int c0 = cg * 4;
    const int r0 = rg * 4;

    const int om = tid & 15;         // out-store: row pair 2om,2om+1
    const int ocg = tid >> 4;        // col group *8

    const long chainOff = (long)chain * (D * D);

    // ---- prologue: A[0] via cp.async ----
    {
        uint32_t s = smem_u32(Ab0) + tid * 16;
        const float* g = A + chainOff + tid * 4;
        #pragma unroll
        for (int i = 0; i < 8; i++) {
            asm volatile("cp.async.cg.shared.global [%0],[%1],16;"
                         :: "r"(s + i * 2048), "l"(g + i * 512));
        }
        asm volatile("cp.async.commit_group;");
    }

    // Bm[0] -> registers (4 rows x 4 cols)
    float4 q0, q1, q2, q3;
    {
        const float* g = Bm + chainOff + (long)(r0base + r0) * D + c0;
        q0 = *(const float4*)(g);
        q1 = *(const float4*)(g + D);
        q2 = *(const float4*)(g + 2 * D);
        q3 = *(const float4*)(g + 3 * D);
    }

    // Init Sb0[k*SROW + r] = S0[r][k]
    {
        int rl = tid & 31;
        int kb = (tid >> 5) * 16;
        const float* g = S0 + chainOff + (long)(r0base + rl) * D + kb;
        #pragma unroll
        for (int kk = 0; kk < 16; kk++)
            Sb0[(kb + kk) * SROW + rl] = g[kk];
    }

    // ---- main time loop ----
    for (int t = 0; t < T_DIM; t++) {
        asm volatile("cp.async.wait_group 0;" ::: "memory");
        __syncthreads();

        const int cur = t & 1;
        float* Acur  = cur ? Ab1 : Ab0;
        float* Anext = cur ? Ab0 : Ab1;
        float* Scur  = cur ? Sb1 : Sb0;
        float* Snext = cur ? Sb0 : Sb1;

        // prefetch A[t+1]
        if (t + 1 < T_DIM) {
            uint32_t s = smem_u32(Anext) + tid * 16;
            const float* g = A + (long)(t + 1) * TSTRIDE + chainOff + tid * 4;
            #pragma unroll
            for (int i = 0; i < 8; i++) {
                asm volatile("cp.async.cg.shared.global [%0],[%1],16;"
                             :: "r"(s + i * 2048), "l"(g + i * 512));
            }
            asm volatile("cp.async.commit_group;");
        }

        // deferred out-store of step t-1 (reads Scur = S_{t-1})
        if (t > 0) {
            uint32_t rb = smem_u32(Scur) + om * 8;
            float v0,v1,v2,v3,v4,v5,v6,v7,v8,v9,v10,v11,v12,v13,v14,v15;
            #define OLD(i, lo, hi) \
                asm("ld.shared.v2.f32 {%0,%1},[%2];" : "=f"(lo), "=f"(hi) \
                    : "r"(rb + (ocg * 8 + i) * (SROW * 4)))
            OLD(0, v0, v1);  OLD(1, v2, v3);  OLD(2, v4, v5);  OLD(3, v6, v7);
            OLD(4, v8, v9);  OLD(5, v10, v11); OLD(6, v12, v13); OLD(7, v14, v15);
            #undef OLD
            float* o = out + (long)(t - 1) * TSTRIDE + chainOff
                     + (long)(r0base + 2 * om) * D + ocg * 8;
            *(float4*)(o)     = make_float4(v0, v2, v4, v6);
            *(float4*)(o + 4) = make_float4(v8, v10, v12, v14);
            *(float4*)(o + D)     = make_float4(v1, v3, v5, v7);
            *(float4*)(o + D + 4) = make_float4(v9, v11, v13, v15);
        }

        // acc := Bm[t] (row-pair packed per column)
        unsigned long long aA0, aA1, aA2, aA3, aB0, aB1, aB2, aB3;
        aA0 = pk2(q0.x, q1.x); aA1 = pk2(q0.y, q1.y);
        aA2 = pk2(q0.z, q1.z); aA3 = pk2(q0.w, q1.w);
        aB0 = pk2(q2.x, q3.x); aB1 = pk2(q2.y, q3.y);
        aB2 = pk2(q2.z, q3.z); aB3 = pk2(q2.w, q3.w);

        // prefetch Bm[t+1]
        if (t + 1 < T_DIM) {
            const float* g = Bm + (long)(t + 1) * TSTRIDE + chainOff
                           + (long)(r0base + r0) * D + c0;
            q0 = *(const float4*)(g);
            q1 = *(const float4*)(g + D);
            q2 = *(const float4*)(g + 2 * D);
            q3 = *(const float4*)(g + 3 * D);
        }

        // ---- k-loop: 16 chunks of 4, 2-stage register double buffer ----
        const uint32_t sA = smem_u32(Scur) + r0 * 4;
        const uint32_t aA = smem_u32(Acur) + c0 * 4;

        unsigned long long sx[2][4], sy[2][4];
        float af[2][4][4];

        #define LOAD1(B, KK, U) do { \
            asm("ld.shared.v2.u64 {%0,%1},[%2];" \
                : "=l"(sx[B][U]), "=l"(sy[B][U]) \
                : "r"(sA + (KK) * (SROW * 4))); \
            asm("ld.shared.v4.f32 {%0,%1,%2,%3},[%4];" \
                : "=f"(af[B][U][0]), "=f"(af[B][U][1]), \
                  "=f"(af[B][U][2]), "=f"(af[B][U][3]) \
                : "r"(aA + (KK) * 256)); \
        } while (0)

        #define LOAD_CHUNK(B, CH) do { \
            LOAD1(B, (CH) * 4 + 0, 0); \
            LOAD1(B, (CH) * 4 + 1, 1); \
            LOAD1(B, (CH) * 4 + 2, 2); \
            LOAD1(B, (CH) * 4 + 3, 3); \
        } while (0)

        #define FMA1(B, U) do { \
            unsigned long long d0 = pk2(af[B][U][0], af[B][U][0]); \
            unsigned long long d1 = pk2(af[B][U][1], af[B][U][1]); \
            unsigned long long d2 = pk2(af[B][U][2], af[B][U][2]); \
            unsigned long long d3 = pk2(af[B][U][3], af[B][U][3]); \
            aA0 = f2fma(sx[B][U], d0, aA0); \
            aA1 = f2fma(sx[B][U], d1, aA1); \
            aA2 = f2fma(sx[B][U], d2, aA2); \
            aA3 = f2fma(sx[B][U], d3, aA3); \
            aB0 = f2fma(sy[B][U], d0, aB0); \
            aB1 = f2fma(sy[B][U], d1, aB1); \
            aB2 = f2fma(sy[B][U], d2, aB2); \
            aB3 = f2fma(sy[B][U], d3, aB3); \
        } while (0)

        #define FMA_CHUNK(B) do { \
            FMA1(B, 0); FMA1(B, 1); FMA1(B, 2); FMA1(B, 3); \
        } while (0)

        LOAD_CHUNK(0, 0);
        #pragma unroll
        for (int ch = 0; ch < 16; ch++) {
            if (ch & 1) {
                if (ch + 1 < 16) LOAD_CHUNK(0, ch + 1);
                FMA_CHUNK(1);
            } else {
                if (ch + 1 < 16) LOAD_CHUNK(1, ch + 1);
                FMA_CHUNK(0);
            }
        }
        #undef LOAD1
        #undef LOAD_CHUNK
        #undef FMA1
        #undef FMA_CHUNK

        // Snew -> Snext[c][r]: acc pairs are already the [c][r0..r0+4] layout
        {
            uint32_t stB = smem_u32(Snext) + c0 * (SROW * 4) + r0 * 4;
            asm volatile("st.shared.v2.u64 [%0],{%1,%2};"
                         :: "r"(stB), "l"(aA0), "l"(aB0));
            asm volatile("st.shared.v2.u64 [%0],{%1,%2};"
                         :: "r"(stB + SROW * 4), "l"(aA1), "l"(aB1));
            asm volatile("st.shared.v2.u64 [%0],{%1,%2};"
                         :: "r"(stB + 2 * SROW * 4), "l"(aA2), "l"(aB2));
            asm volatile("st.shared.v2.u64 [%0],{%1,%2};"
                         :: "r"(stB + 3 * SROW * 4), "l"(aA3), "l"(aB3));
        }
    }

    // final out-store for t = T-1
    __syncthreads();
    {
        float* Slast = (T_DIM & 1) ? Sb1 : Sb0;
        uint32_t rb = smem_u32(Slast) + om * 8;
        float v0,v1,v2,v3,v4,v5,v6,v7,v8,v9,v10,v11,v12,v13,v14,v15;
        #define OLD(i, lo, hi) \
            asm("ld.shared.v2.f32 {%0,%1},[%2];" : "=f"(lo), "=f"(hi) \
                : "r"(rb + (ocg * 8 + i) * (SROW * 4)))
        OLD(0, v0, v1);  OLD(1, v2, v3);  OLD(2, v4, v5);  OLD(3, v6, v7);
        OLD(4, v8, v9);  OLD(5, v10, v11); OLD(6, v12, v13); OLD(7, v14, v15);
        #undef OLD
        float* o = out + (long)(T_DIM - 1) * TSTRIDE + chainOff
                 + (long)(r0base + 2 * om) * D + ocg * 8;
        *(float4*)(o)     = make_float4(v0, v2, v4, v6);
        *(float4*)(o + 4) = make_float4(v8, v10, v12, v14);
        *(float4*)(o + D)     = make_float4(v1, v3, v5, v7);
        *(float4*)(o + D + 4) = make_float4(v9, v11, v13, v15);
    }
}

extern "C" void kernel_launch(void* const* d_in, const int* in_sizes, int n_in,
                              void* d_out, int out_size) {
    const float* A  = (const float*)d_in[0];
    const float* Bm = (const float*)d_in[1];
    const float* S0 = (const float*)d_in[2];
    float* out = (float*)d_out;
    (void)in_sizes; (void)n_in; (void)out_size;

    cudaFuncSetAttribute(gdr_kernel,
                         cudaFuncAttributeMaxDynamicSharedMemorySize,
                         SMEM_BYTES);
    gdr_kernel<<<BH * 2, THREADS, SMEM_BYTES>>>(A, Bm, S0, out);
}